// round 12
// baseline (speedup 1.0000x reference)
#include <cuda_runtime.h>

// RoIAlign (FPN, 4 levels) + fused 2x2 stride-1 avg epilogue.
// Grid: 2 blocks per roi (channel slices of 128), 256 thr = 8 warps/block.
// Each warp owns 16 channels (channels-per-warp maximized: proven dominant
// knob). Loop order: OUTER over 7 pooled rows (py), INNER unrolled over the
// 16 channels -> smem y-descriptors read once per py for 16 channels, and
// each py issues 48-64 independent gathers (deep MLP) that overlap the
// previous py's shuffle reductions.
// Lane l (<28) owns x-tap column l = 2*t + k. Fast path (rh <= 14 px):
// pooled row's 4 bilinear rows fit a 3-row window -> <=3 loads.
// Epilogue: out[py-1,px] = 8-lane window sum (shfl_down 1,2,4) of
// (v[py-1]+v[py])*wcol, 1/16 folded into wcol.

namespace {
constexpr int C = 256;

__global__ __launch_bounds__(256, 3)
void roialign_kernel(const float* __restrict__ f0, const float* __restrict__ f1,
                     const float* __restrict__ f2, const float* __restrict__ f3,
                     const float* __restrict__ rois, float* __restrict__ out)
{
    const int roi   = blockIdx.x >> 1;
    const int slice = blockIdx.x & 1;       // 128-channel slice
    const int b = roi >> 9;                 // N = 512
    const float* r = rois + roi * 7;

    __shared__ int    scol[32];             // column index per lane (clamped)
    __shared__ float  swx[32];              // x-weight per lane (0 if invalid)
    __shared__ float4 sy[14];               // {off0, off1 (int bits), wy0, wy1}
    __shared__ float4 spy[7];               // fast: {baseOff bits, w0, w1, w2}

    const int tid = threadIdx.x;
    const int lev = (int)r[6];
    const int Wd = 160 >> lev;
    const float scale = 8.0f / (float)(1 << lev);

    // uniform fast-path condition: sample stride rh/14 <= 1
    const float rh_u = fmaxf((r[4] - r[2]) * scale, 1.0f);
    const bool fast = (rh_u <= 14.0f);

    if (tid < 32) {                         // x-tap setup: lane l = 2*t + k
        int l = min(tid, 27);               // idle lanes alias lane 27
        int t = l >> 1, k = l & 1;
        const float c1 = r[1] * scale;
        const float c2 = r[3] * scale;
        const float bin = fmaxf(c2 - c1, 1.0f) * (1.0f / 7.0f);
        const float off = (float)(t >> 1) + ((t & 1) ? 0.75f : 0.25f);
        const float pos = c1 + off * bin;
        const bool valid = (pos >= -1.0f) && (pos <= (float)Wd);
        const float p = fminf(fmaxf(pos, 0.0f), (float)(Wd - 1));
        const float p0 = floorf(p);
        const int i0 = (int)p0;
        const int i1 = min(i0 + 1, Wd - 1);
        const float lx = p - p0;
        scol[tid] = k ? i1 : i0;
        // fold the 2x2-avg-pool scale (1/16) into the x weight
        swx[tid] = (tid < 28 && valid) ? 0.0625f * (k ? lx : 1.0f - lx) : 0.0f;
    } else if (tid < 46) {                  // y-sample setup: s = tid - 32
        const int s = tid - 32;
        const float c1 = r[2] * scale;
        const float c2 = r[4] * scale;
        const float bin = fmaxf(c2 - c1, 1.0f) * (1.0f / 7.0f);
        const float off = (float)(s >> 1) + ((s & 1) ? 0.75f : 0.25f);
        const float pos = c1 + off * bin;
        const bool valid = (pos >= -1.0f) && (pos <= (float)Wd);
        const float p = fminf(fmaxf(pos, 0.0f), (float)(Wd - 1));
        const float p0 = floorf(p);
        const int i0 = (int)p0;
        const int i1 = min(i0 + 1, Wd - 1);
        const float ly = p - p0;
        float4 v;
        v.x = __int_as_float(i0 * Wd);
        v.y = __int_as_float(i1 * Wd);
        v.z = valid ? (1.0f - ly) : 0.0f;
        v.w = valid ? ly : 0.0f;
        sy[s] = v;
    } else if (tid < 53 && fast) {          // fast-path 3-row windows, py = tid-46
        const int py = tid - 46;
        const float c1 = r[2] * scale;
        const float c2 = r[4] * scale;
        const float bin = fmaxf(c2 - c1, 1.0f) * (1.0f / 7.0f);
        float w[3] = {0.0f, 0.0f, 0.0f};
        int base = 0;
        #pragma unroll
        for (int h = 0; h < 2; ++h) {
            const int s = 2 * py + h;
            const float off = (float)(s >> 1) + ((s & 1) ? 0.75f : 0.25f);
            const float pos = c1 + off * bin;
            const bool valid = (pos >= -1.0f) && (pos <= (float)Wd);
            const float p = fminf(fmaxf(pos, 0.0f), (float)(Wd - 1));
            const float p0 = floorf(p);
            const int i0 = (int)p0;
            const int i1 = min(i0 + 1, Wd - 1);
            const float ly = p - p0;
            if (h == 0) base = i0;          // rows monotone within the bin
            w[i0 - base] += valid ? (1.0f - ly) : 0.0f;
            w[i1 - base] += valid ? ly : 0.0f;
        }
        float4 e;
        e.x = __int_as_float(base * Wd);
        e.y = w[0]; e.z = w[1]; e.w = w[2];
        spy[py] = e;
    }
    __syncthreads();

    const float* fb = (lev == 0) ? f0 : (lev == 1) ? f1 : (lev == 2) ? f2 : f3;
    const int HW = Wd * Wd;
    const int warp = tid >> 5;
    const int lane = tid & 31;

    const int mycol = scol[lane];
    const float wcol = swx[lane];
    const bool active = (lane & 3) == 0 && lane < 24;
    const int px = lane >> 2;               // 0..5 when active
    const int cbase = slice * 128 + warp * 16;
    const float* fc0 = fb + (size_t)(b * C + cbase) * HW + mycol;
    float* op0 = out + (size_t)roi * (C * 36) + cbase * 36 + px;

    float prev[16];
    #pragma unroll 1
    for (int py = 0; py < 7; ++py) {
        float v[16];
        if (fast) {
            const float4 e = spy[py];
            const int bo = __float_as_int(e.x);
            const bool h0 = (e.y != 0.0f);
            const bool h1 = (e.z != 0.0f);
            const bool h2 = (e.w != 0.0f);
            #pragma unroll
            for (int ch = 0; ch < 16; ++ch) {
                const float* fc = fc0 + ch * HW;
                float a = 0.0f;
                if (h0) a += e.y * __ldg(fc + bo);
                if (h1) a += e.z * __ldg(fc + bo + Wd);
                if (h2) a += e.w * __ldg(fc + bo + 2 * Wd);
                v[ch] = a;
            }
        } else {
            const float4 y0 = sy[2 * py];
            const float4 y1 = sy[2 * py + 1];
            const int o00 = __float_as_int(y0.x);
            const int o01 = __float_as_int(y0.y);
            const int o10 = __float_as_int(y1.x);
            const int o11 = __float_as_int(y1.y);
            #pragma unroll
            for (int ch = 0; ch < 16; ++ch) {
                const float* fc = fc0 + ch * HW;
                const float a00 = __ldg(fc + o00);
                const float a01 = __ldg(fc + o01);
                const float a10 = __ldg(fc + o10);
                const float a11 = __ldg(fc + o11);
                v[ch] = y0.z * a00 + y0.w * a01 + y1.z * a10 + y1.w * a11;
            }
        }
        if (py > 0) {
            #pragma unroll
            for (int ch = 0; ch < 16; ++ch) {
                float u = (prev[ch] + v[ch]) * wcol;
                u += __shfl_down_sync(0xFFFFFFFFu, u, 1);
                u += __shfl_down_sync(0xFFFFFFFFu, u, 2);
                u += __shfl_down_sync(0xFFFFFFFFu, u, 4);
                if (active)
                    op0[ch * 36 + (py - 1) * 6] = u;
            }
        }
        #pragma unroll
        for (int ch = 0; ch < 16; ++ch) prev[ch] = v[ch];
    }
}
} // namespace

extern "C" void kernel_launch(void* const* d_in, const int* in_sizes, int n_in,
                              void* d_out, int out_size) {
    const float* f0   = (const float*)d_in[0];
    const float* f1   = (const float*)d_in[1];
    const float* f2   = (const float*)d_in[2];
    const float* f3   = (const float*)d_in[3];
    const float* rois = (const float*)d_in[4];
    const int nroi = in_sizes[4] / 7;       // B*N = 1024
    roialign_kernel<<<nroi * 2, 256>>>(f0, f1, f2, f3, rois, (float*)d_out);
}

// round 13
// speedup vs baseline: 1.2890x; 1.2890x over previous
#include <cuda_runtime.h>

// RoIAlign (FPN, 4 levels) + fused 2x2 stride-1 avg epilogue.
// Grid: 4 blocks per roi (channel slices of 64), 256 thr = 8 warps/block.
// Each warp owns 8 channels (confirmed optimum: 4 and 16 both regress).
// Loop order: OUTER over the 7 pooled rows (py) -- FULLY UNROLLED so ptxas
// can software-pipeline: the next row's independent gathers get scheduled
// above the previous row's shuffle-reduction chain, and the prev=v register
// shifts become SSA renames. INNER unrolled over the 8 channels (smem
// y-descriptors read once per py, ~32 independent loads in flight per warp,
// inside the ~55 per-warp LDG limit).
// Lane l (<28) owns x-tap column l = 2*t + k. Fast path (rh <= 14 px):
// pooled row's 4 bilinear rows fit a 3-row window -> <=3 loads.
// Epilogue: out[py-1,px] = 8-lane window sum (shfl_down 1,2,4) of
// (v[py-1]+v[py])*wcol, 1/16 folded into wcol.

namespace {
constexpr int C = 256;

__global__ __launch_bounds__(256, 4)
void roialign_kernel(const float* __restrict__ f0, const float* __restrict__ f1,
                     const float* __restrict__ f2, const float* __restrict__ f3,
                     const float* __restrict__ rois, float* __restrict__ out)
{
    const int roi   = blockIdx.x >> 2;
    const int slice = blockIdx.x & 3;       // 64-channel slice
    const int b = roi >> 9;                 // N = 512
    const float* r = rois + roi * 7;

    __shared__ int    scol[32];             // column index per lane (clamped)
    __shared__ float  swx[32];              // x-weight per lane (0 if invalid)
    __shared__ float4 sy[14];               // {off0, off1 (int bits), wy0, wy1}
    __shared__ float4 spy[7];               // fast: {baseOff bits, w0, w1, w2}

    const int tid = threadIdx.x;
    const int lev = (int)r[6];
    const int Wd = 160 >> lev;
    const float scale = 8.0f / (float)(1 << lev);

    // uniform fast-path condition: sample stride rh/14 <= 1
    const float rh_u = fmaxf((r[4] - r[2]) * scale, 1.0f);
    const bool fast = (rh_u <= 14.0f);

    if (tid < 32) {                         // x-tap setup: lane l = 2*t + k
        int l = min(tid, 27);               // idle lanes alias lane 27
        int t = l >> 1, k = l & 1;
        const float c1 = r[1] * scale;
        const float c2 = r[3] * scale;
        const float bin = fmaxf(c2 - c1, 1.0f) * (1.0f / 7.0f);
        const float off = (float)(t >> 1) + ((t & 1) ? 0.75f : 0.25f);
        const float pos = c1 + off * bin;
        const bool valid = (pos >= -1.0f) && (pos <= (float)Wd);
        const float p = fminf(fmaxf(pos, 0.0f), (float)(Wd - 1));
        const float p0 = floorf(p);
        const int i0 = (int)p0;
        const int i1 = min(i0 + 1, Wd - 1);
        const float lx = p - p0;
        scol[tid] = k ? i1 : i0;
        // fold the 2x2-avg-pool scale (1/16) into the x weight
        swx[tid] = (tid < 28 && valid) ? 0.0625f * (k ? lx : 1.0f - lx) : 0.0f;
    } else if (tid < 46) {                  // y-sample setup: s = tid - 32
        const int s = tid - 32;
        const float c1 = r[2] * scale;
        const float c2 = r[4] * scale;
        const float bin = fmaxf(c2 - c1, 1.0f) * (1.0f / 7.0f);
        const float off = (float)(s >> 1) + ((s & 1) ? 0.75f : 0.25f);
        const float pos = c1 + off * bin;
        const bool valid = (pos >= -1.0f) && (pos <= (float)Wd);
        const float p = fminf(fmaxf(pos, 0.0f), (float)(Wd - 1));
        const float p0 = floorf(p);
        const int i0 = (int)p0;
        const int i1 = min(i0 + 1, Wd - 1);
        const float ly = p - p0;
        float4 v;
        v.x = __int_as_float(i0 * Wd);
        v.y = __int_as_float(i1 * Wd);
        v.z = valid ? (1.0f - ly) : 0.0f;
        v.w = valid ? ly : 0.0f;
        sy[s] = v;
    } else if (tid < 53 && fast) {          // fast-path 3-row windows, py = tid-46
        const int py = tid - 46;
        const float c1 = r[2] * scale;
        const float c2 = r[4] * scale;
        const float bin = fmaxf(c2 - c1, 1.0f) * (1.0f / 7.0f);
        float w[3] = {0.0f, 0.0f, 0.0f};
        int base = 0;
        #pragma unroll
        for (int h = 0; h < 2; ++h) {
            const int s = 2 * py + h;
            const float off = (float)(s >> 1) + ((s & 1) ? 0.75f : 0.25f);
            const float pos = c1 + off * bin;
            const bool valid = (pos >= -1.0f) && (pos <= (float)Wd);
            const float p = fminf(fmaxf(pos, 0.0f), (float)(Wd - 1));
            const float p0 = floorf(p);
            const int i0 = (int)p0;
            const int i1 = min(i0 + 1, Wd - 1);
            const float ly = p - p0;
            if (h == 0) base = i0;          // rows monotone within the bin
            w[i0 - base] += valid ? (1.0f - ly) : 0.0f;
            w[i1 - base] += valid ? ly : 0.0f;
        }
        float4 e;
        e.x = __int_as_float(base * Wd);
        e.y = w[0]; e.z = w[1]; e.w = w[2];
        spy[py] = e;
    }
    __syncthreads();

    const float* fb = (lev == 0) ? f0 : (lev == 1) ? f1 : (lev == 2) ? f2 : f3;
    const int HW = Wd * Wd;
    const int warp = tid >> 5;
    const int lane = tid & 31;

    const int mycol = scol[lane];
    const float wcol = swx[lane];
    const bool active = (lane & 3) == 0 && lane < 24;
    const int px = lane >> 2;               // 0..5 when active
    const int cbase = slice * 64 + warp * 8;
    const float* fc0 = fb + (size_t)(b * C + cbase) * HW + mycol;
    float* op0 = out + (size_t)roi * (C * 36) + cbase * 36 + px;

    if (fast) {
        float prev[8];
        #pragma unroll
        for (int py = 0; py < 7; ++py) {
            float v[8];
            const float4 e = spy[py];
            const int bo = __float_as_int(e.x);
            const bool h0 = (e.y != 0.0f);
            const bool h1 = (e.z != 0.0f);
            const bool h2 = (e.w != 0.0f);
            #pragma unroll
            for (int ch = 0; ch < 8; ++ch) {
                const float* fc = fc0 + ch * HW;
                float a = 0.0f;
                if (h0) a += e.y * __ldg(fc + bo);
                if (h1) a += e.z * __ldg(fc + bo + Wd);
                if (h2) a += e.w * __ldg(fc + bo + 2 * Wd);
                v[ch] = a;
            }
            if (py > 0) {
                #pragma unroll
                for (int ch = 0; ch < 8; ++ch) {
                    float u = (prev[ch] + v[ch]) * wcol;
                    u += __shfl_down_sync(0xFFFFFFFFu, u, 1);
                    u += __shfl_down_sync(0xFFFFFFFFu, u, 2);
                    u += __shfl_down_sync(0xFFFFFFFFu, u, 4);
                    if (active)
                        op0[ch * 36 + (py - 1) * 6] = u;
                }
            }
            #pragma unroll
            for (int ch = 0; ch < 8; ++ch) prev[ch] = v[ch];
        }
    } else {
        float prev[8];
        #pragma unroll
        for (int py = 0; py < 7; ++py) {
            float v[8];
            const float4 y0 = sy[2 * py];
            const float4 y1 = sy[2 * py + 1];
            const int o00 = __float_as_int(y0.x);
            const int o01 = __float_as_int(y0.y);
            const int o10 = __float_as_int(y1.x);
            const int o11 = __float_as_int(y1.y);
            #pragma unroll
            for (int ch = 0; ch < 8; ++ch) {
                const float* fc = fc0 + ch * HW;
                const float a00 = __ldg(fc + o00);
                const float a01 = __ldg(fc + o01);
                const float a10 = __ldg(fc + o10);
                const float a11 = __ldg(fc + o11);
                v[ch] = y0.z * a00 + y0.w * a01 + y1.z * a10 + y1.w * a11;
            }
            if (py > 0) {
                #pragma unroll
                for (int ch = 0; ch < 8; ++ch) {
                    float u = (prev[ch] + v[ch]) * wcol;
                    u += __shfl_down_sync(0xFFFFFFFFu, u, 1);
                    u += __shfl_down_sync(0xFFFFFFFFu, u, 2);
                    u += __shfl_down_sync(0xFFFFFFFFu, u, 4);
                    if (active)
                        op0[ch * 36 + (py - 1) * 6] = u;
                }
            }
            #pragma unroll
            for (int ch = 0; ch < 8; ++ch) prev[ch] = v[ch];
        }
    }
}
} // namespace

extern "C" void kernel_launch(void* const* d_in, const int* in_sizes, int n_in,
                              void* d_out, int out_size) {
    const float* f0   = (const float*)d_in[0];
    const float* f1   = (const float*)d_in[1];
    const float* f2   = (const float*)d_in[2];
    const float* f3   = (const float*)d_in[3];
    const float* rois = (const float*)d_in[4];
    const int nroi = in_sizes[4] / 7;       // B*N = 1024
    roialign_kernel<<<nroi * 4, 256>>>(f0, f1, f2, f3, rois, (float*)d_out);
}